// round 9
// baseline (speedup 1.0000x reference)
#include <cuda_runtime.h>
#include <math.h>

#define B_   4
#define S_   512
#define K_   32
#define V_   32000
#define ROWS (B_*S_)
#define NT   256
#define NW   (NT/32)
#define NF4  (V_/4)

#define CMP2(x, y) { float _hi = fmaxf((x),(y)), _lo = fminf((x),(y)); (x) = _hi; (y) = _lo; }

// Sort 4 values descending: optimal 5-comparator network.
__device__ __forceinline__ void sort4_desc(float* v) {
    CMP2(v[0], v[1]); CMP2(v[2], v[3]);
    CMP2(v[0], v[2]); CMP2(v[1], v[3]);
    CMP2(v[1], v[2]);
}

// Merge two descending sorted-4 lists into descending sorted-8 (bitonic, 12 comparators).
__device__ __forceinline__ void merge44_desc(const float* p, const float* q, float* x) {
    x[0] = p[0]; x[1] = p[1]; x[2] = p[2]; x[3] = p[3];
    x[4] = q[3]; x[5] = q[2]; x[6] = q[1]; x[7] = q[0];   // desc ++ asc = bitonic
    CMP2(x[0], x[4]); CMP2(x[1], x[5]); CMP2(x[2], x[6]); CMP2(x[3], x[7]);
    CMP2(x[0], x[2]); CMP2(x[1], x[3]); CMP2(x[4], x[6]); CMP2(x[5], x[7]);
    CMP2(x[0], x[1]); CMP2(x[2], x[3]); CMP2(x[4], x[5]); CMP2(x[6], x[7]);
}

// Top-8 of two descending-sorted 8-lists, result descending into r (8 max + 12 cmp).
__device__ __forceinline__ void top8_of_two8(const float* a, const float* b, float* r) {
    #pragma unroll
    for (int j = 0; j < 8; ++j) r[j] = fmaxf(a[j], b[7 - j]);   // bitonic top-half
    CMP2(r[0], r[4]); CMP2(r[1], r[5]); CMP2(r[2], r[6]); CMP2(r[3], r[7]);
    CMP2(r[0], r[2]); CMP2(r[1], r[3]); CMP2(r[4], r[6]); CMP2(r[5], r[7]);
    CMP2(r[0], r[1]); CMP2(r[2], r[3]); CMP2(r[4], r[5]); CMP2(r[6], r[7]);
}

// In-place: t = top8(t, b) with both descending.
__device__ __forceinline__ void bitonic_top8_merge(float* t, const float* b) {
    float m[8];
    top8_of_two8(t, b, m);
    #pragma unroll
    for (int j = 0; j < 8; ++j) t[j] = m[j];
}

// Sorted top-8 of 16 raw values (independent of t).
__device__ __forceinline__ void top8_of16(float4 a, float4 b, float4 c, float4 d, float* u) {
    float va[4] = {a.x, a.y, a.z, a.w};
    float vb[4] = {b.x, b.y, b.z, b.w};
    float vc[4] = {c.x, c.y, c.z, c.w};
    float vd[4] = {d.x, d.y, d.z, d.w};
    sort4_desc(va); sort4_desc(vb); sort4_desc(vc); sort4_desc(vd);
    float s1[8], s2[8];
    merge44_desc(va, vb, s1);
    merge44_desc(vc, vd, s2);
    top8_of_two8(s1, s2, u);
}

// Fold 16 values into running descending top-8 t: one short t-chain.
__device__ __forceinline__ void fold16(float4 a, float4 b, float4 c, float4 d, float* t) {
    float u[8];
    top8_of16(a, b, c, d, u);
    bitonic_top8_merge(t, u);
}

// Tail-only rare insert.
__device__ __forceinline__ void insert1(float x, float* t) {
    if (x > t[7]) {
        t[7] = x;
        #pragma unroll
        for (int j = 7; j > 0; --j)
            if (t[j] > t[j - 1]) { float tm = t[j - 1]; t[j - 1] = t[j]; t[j] = tm; }
    }
}

__global__ void __launch_bounds__(NT)
combiner_kernel(const int*   __restrict__ tgt,
                const float* __restrict__ dists,
                const float* __restrict__ keyf,
                const float* __restrict__ nprob,
                const float* __restrict__ selp,
                const float* __restrict__ Wf,  const float* __restrict__ bf,
                const float* __restrict__ W1a, const float* __restrict__ b1a,
                const float* __restrict__ W1b, const float* __restrict__ b1b,
                const float* __restrict__ W2a, const float* __restrict__ b2a,
                const float* __restrict__ W2b, const float* __restrict__ b2b,
                float* __restrict__ out, float* __restrict__ lam_out)
{
    const int row  = blockIdx.x;
    const int tid  = threadIdx.x;
    const int lane = tid & 31;
    const int warp = tid >> 5;
    const unsigned FULL = 0xffffffffu;

    __shared__ float s_d[K_], s_lk[K_], s_ls[K_], s_cnt[K_], s_probs[K_];
    __shared__ int   s_idx[K_];
    __shared__ float s_warp[NW][8];
    __shared__ float s_top8[8];
    __shared__ float s_lam;

    // ---- Phase 1 (warp 0): per-row small inputs + distinct-label prefix counts
    if (warp == 0) {
        const int base = row * K_;
        int v = tgt[base + lane];
        s_idx[lane] = v;
        s_d[lane]  = dists[base + lane];
        s_lk[lane] = logf(keyf[base + lane]);
        s_ls[lane] = logf(selp[base + lane]);
        bool dup = false;
        #pragma unroll
        for (int j = 0; j < 31; ++j) {
            int vj = __shfl_sync(FULL, v, j);
            if (j < lane && vj == v) dup = true;
        }
        unsigned m = __ballot_sync(FULL, (v != 0) && !dup);
        s_cnt[lane] = (float)__popc(m & ((2u << lane) - 1u));
    }

    // ---- Phase 2: READ-ONLY software-pipelined streaming top-8 scan
    // (output zeroing is done by a separate memset node at pure-write BW)
    const float4* src = reinterpret_cast<const float4*>(nprob + (size_t)row * V_);

    int i = tid;
    float4 a0 = __ldcs(src + i);
    float4 b0 = __ldcs(src + i + NT);
    float4 c0 = __ldcs(src + i + 2 * NT);
    float4 d0 = __ldcs(src + i + 3 * NT);

    float t[8];
    {
        int ni = i + 4 * NT;
        float4 a1 = __ldcs(src + ni);
        float4 b1 = __ldcs(src + ni + NT);
        float4 c1 = __ldcs(src + ni + 2 * NT);
        float4 d1 = __ldcs(src + ni + 3 * NT);
        top8_of16(a0, b0, c0, d0, t);   // seed: t = sorted top8 of first 16
        a0 = a1; b0 = b1; c0 = c1; d0 = d1; i = ni;
    }
    #pragma unroll 1
    for (int ii = 1; ii < 6; ++ii) {
        int ni = i + 4 * NT;
        float4 a1 = __ldcs(src + ni);
        float4 b1 = __ldcs(src + ni + NT);
        float4 c1 = __ldcs(src + ni + 2 * NT);
        float4 d1 = __ldcs(src + ni + 3 * NT);
        fold16(a0, b0, c0, d0, t);
        a0 = a1; b0 = b1; c0 = c1; d0 = d1; i = ni;
    }
    fold16(a0, b0, c0, d0, t);   // iter 6, no prefetch
    i += 4 * NT;

    #pragma unroll 1
    for (; i < NF4; i += NT) {   // tail: 3 strided iters + partial (tid < 64)
        float4 a = __ldcs(src + i);
        float m4 = fmaxf(fmaxf(a.x, a.y), fmaxf(a.z, a.w));
        if (m4 > t[7]) { insert1(a.x, t); insert1(a.y, t); insert1(a.z, t); insert1(a.w, t); }
    }

    // ---- Phase 3: register/shuffle top-8 reduction
    #pragma unroll
    for (int off = 16; off >= 1; off >>= 1) {
        float b[8];
        #pragma unroll
        for (int j = 0; j < 8; ++j) b[j] = __shfl_down_sync(FULL, t[j], off);
        bitonic_top8_merge(t, b);
    }
    if (lane == 0) {
        #pragma unroll
        for (int j = 0; j < 8; ++j) s_warp[warp][j] = t[j];
    }
    __syncthreads();

    if (warp == 0) {
        float w[8];
        #pragma unroll
        for (int j = 0; j < 8; ++j) w[j] = (lane < NW) ? s_warp[lane & (NW - 1)][j] : -1.0f;
        #pragma unroll
        for (int off = 4; off >= 1; off >>= 1) {
            float b[8];
            #pragma unroll
            for (int j = 0; j < 8; ++j) b[j] = __shfl_down_sync(FULL, w[j], off);
            bitonic_top8_merge(w, b);
        }
        if (lane == 0) {
            #pragma unroll
            for (int j = 0; j < 8; ++j) s_top8[j] = w[j];
        }
        __syncwarp();

        // ---- Phase 4 (warp 0): MLPs, softmax, lambda
        float lk = s_lk[lane], ls = s_ls[lane], d = s_d[lane];

        float nl = b1b[0];
        #pragma unroll
        for (int j = 0; j < 4; ++j) {
            float h = tanhf(fmaf(W1a[2 * j], lk, fmaf(W1a[2 * j + 1], ls, b1a[j])));
            nl = fmaf(W1b[j], h, nl);
        }

        float acc = b2a[lane];
        #pragma unroll
        for (int dd = 0; dd < 32; ++dd) acc = fmaf(W2a[lane * 64 + dd],      s_d[dd],   acc);
        #pragma unroll
        for (int dd = 0; dd < 32; ++dd) acc = fmaf(W2a[lane * 64 + 32 + dd], s_cnt[dd], acc);
        float h2 = tanhf(acc);
        float l0 = W2b[lane]      * h2;
        float l1 = W2b[32 + lane] * h2;

        float sp = fmaf(Wf[8 + lane], lk, Wf[40 + lane] * ls);
        if (lane < 8) sp = fmaf(Wf[lane], logf(s_top8[lane]), sp);

        #pragma unroll
        for (int o = 16; o >= 1; o >>= 1) {
            l0 += __shfl_xor_sync(FULL, l0, o);
            l1 += __shfl_xor_sync(FULL, l1, o);
            sp += __shfl_xor_sync(FULL, sp, o);
        }
        l0 += b2b[0]; l1 += b2b[1];
        float sim   = sp + bf[0];
        float tempe = 1.f / (1.f + expf(-l1));

        float z  = fmaf(-d, tempe, nl);
        float mx = z;
        #pragma unroll
        for (int o = 16; o >= 1; o >>= 1) mx = fmaxf(mx, __shfl_xor_sync(FULL, mx, o));
        float e  = expf(z - mx);
        float se = e;
        #pragma unroll
        for (int o = 16; o >= 1; o >>= 1) se += __shfl_xor_sync(FULL, se, o);
        s_probs[lane] = e / se;

        if (lane == 0) s_lam = 1.f / (1.f + expf(-(l0 - sim)));

        __syncwarp();

        // ---- Phase 5: ordered scatter (last-wins for duplicates) + lambda
        // Output row was zeroed by the memset node (stream-ordered before us).
        if (lane == 0) {
            float* orow = out + (size_t)row * V_;
            #pragma unroll
            for (int k = 0; k < K_; ++k) orow[s_idx[k]] = s_probs[k];
            lam_out[row] = s_lam;
        }
    }
}

extern "C" void kernel_launch(void* const* d_in, const int* in_sizes, int n_in,
                              void* d_out, int out_size) {
    const int*   tgt   = (const int*)  d_in[0];
    const float* dists = (const float*)d_in[1];
    const float* keyf  = (const float*)d_in[2];
    const float* nprob = (const float*)d_in[3];
    const float* selp  = (const float*)d_in[4];
    const float* Wf    = (const float*)d_in[5];
    const float* bf    = (const float*)d_in[6];
    const float* W1a   = (const float*)d_in[7];
    const float* b1a   = (const float*)d_in[8];
    const float* W1b   = (const float*)d_in[9];
    const float* b1b   = (const float*)d_in[10];
    const float* W2a   = (const float*)d_in[11];
    const float* b2a   = (const float*)d_in[12];
    const float* W2b   = (const float*)d_in[13];
    const float* b2b   = (const float*)d_in[14];

    float* out = (float*)d_out;
    float* lam = out + ((size_t)out_size - ROWS);

    // Zero knn_prob at pure-write bandwidth; stream order guarantees
    // completion before the scan kernel's scatter.
    cudaMemsetAsync(out, 0, (size_t)ROWS * V_ * sizeof(float));

    combiner_kernel<<<ROWS, NT>>>(tgt, dists, keyf, nprob, selp,
                                  Wf, bf, W1a, b1a, W1b, b1b,
                                  W2a, b2a, W2b, b2b, out, lam);
}

// round 12
// speedup vs baseline: 1.1134x; 1.1134x over previous
#include <cuda_runtime.h>
#include <cuda_bf16.h>
#include <math.h>

#define B_   4
#define S_   512
#define K_   32
#define V_   32000
#define ROWS (B_*S_)
#define NT   256
#define NW   (NT/32)
#define NF4  (V_/4)

// ---------- packed bf16x2 comparator primitives (two streams per register) ----
__device__ __forceinline__ unsigned bmax2(unsigned a, unsigned b) {
    __nv_bfloat162 r = __hmax2(*reinterpret_cast<__nv_bfloat162*>(&a),
                               *reinterpret_cast<__nv_bfloat162*>(&b));
    return *reinterpret_cast<unsigned*>(&r);
}
__device__ __forceinline__ unsigned bmin2(unsigned a, unsigned b) {
    __nv_bfloat162 r = __hmin2(*reinterpret_cast<__nv_bfloat162*>(&a),
                               *reinterpret_cast<__nv_bfloat162*>(&b));
    return *reinterpret_cast<unsigned*>(&r);
}
#define CMP2P(x, y) { unsigned _hi = bmax2((x),(y)), _lo = bmin2((x),(y)); (x) = _hi; (y) = _lo; }
#define CMP2F(x, y) { float _hi = fmaxf((x),(y)), _lo = fminf((x),(y)); (x) = _hi; (y) = _lo; }

// pack hi-16 bits of two positive floats: lo half = bf16-trunc(x), hi half = bf16-trunc(y)
__device__ __forceinline__ unsigned packhi(float x, float y) {
    return __byte_perm(__float_as_uint(x), __float_as_uint(y), 0x7632);
}

// Sort 4 packed descending (per half): 5 comparators.
__device__ __forceinline__ void sort4p(unsigned* v) {
    CMP2P(v[0], v[1]); CMP2P(v[2], v[3]);
    CMP2P(v[0], v[2]); CMP2P(v[1], v[3]);
    CMP2P(v[1], v[2]);
}
// Merge two descending sorted-4 packed into descending sorted-8 (12 comparators).
__device__ __forceinline__ void merge44p(const unsigned* p, const unsigned* q, unsigned* x) {
    x[0] = p[0]; x[1] = p[1]; x[2] = p[2]; x[3] = p[3];
    x[4] = q[3]; x[5] = q[2]; x[6] = q[1]; x[7] = q[0];
    CMP2P(x[0], x[4]); CMP2P(x[1], x[5]); CMP2P(x[2], x[6]); CMP2P(x[3], x[7]);
    CMP2P(x[0], x[2]); CMP2P(x[1], x[3]); CMP2P(x[4], x[6]); CMP2P(x[5], x[7]);
    CMP2P(x[0], x[1]); CMP2P(x[2], x[3]); CMP2P(x[4], x[5]); CMP2P(x[6], x[7]);
}
// t = top8(t, b), both descending packed (8 max + 12 comparators).
__device__ __forceinline__ void top8_merge_p(unsigned* t, const unsigned* b) {
    unsigned m[8];
    #pragma unroll
    for (int j = 0; j < 8; ++j) m[j] = bmax2(t[j], b[7 - j]);
    CMP2P(m[0], m[4]); CMP2P(m[1], m[5]); CMP2P(m[2], m[6]); CMP2P(m[3], m[7]);
    CMP2P(m[0], m[2]); CMP2P(m[1], m[3]); CMP2P(m[4], m[6]); CMP2P(m[5], m[7]);
    CMP2P(m[0], m[1]); CMP2P(m[2], m[3]); CMP2P(m[4], m[5]); CMP2P(m[6], m[7]);
    #pragma unroll
    for (int j = 0; j < 8; ++j) t[j] = m[j];
}
// Fold 8 packed (=16 floats) into running packed top-8.
__device__ __forceinline__ void fold8p(unsigned* p, unsigned* t) {
    sort4p(p); sort4p(p + 4);
    unsigned s[8];
    merge44p(p, p + 4, s);
    top8_merge_p(t, s);
}

// ---------- f32 merge for the cross-thread reduction ----------
__device__ __forceinline__ void top8_of_two8f(const float* a, const float* b, float* r) {
    #pragma unroll
    for (int j = 0; j < 8; ++j) r[j] = fmaxf(a[j], b[7 - j]);
    CMP2F(r[0], r[4]); CMP2F(r[1], r[5]); CMP2F(r[2], r[6]); CMP2F(r[3], r[7]);
    CMP2F(r[0], r[2]); CMP2F(r[1], r[3]); CMP2F(r[4], r[6]); CMP2F(r[5], r[7]);
    CMP2F(r[0], r[1]); CMP2F(r[2], r[3]); CMP2F(r[4], r[5]); CMP2F(r[6], r[7]);
}
__device__ __forceinline__ void merge8f(float* t, const float* b) {
    float m[8];
    top8_of_two8f(t, b, m);
    #pragma unroll
    for (int j = 0; j < 8; ++j) t[j] = m[j];
}

__global__ void __launch_bounds__(NT)
combiner_kernel(const int*   __restrict__ tgt,
                const float* __restrict__ dists,
                const float* __restrict__ keyf,
                const float* __restrict__ nprob,
                const float* __restrict__ selp,
                const float* __restrict__ Wf,  const float* __restrict__ bf,
                const float* __restrict__ W1a, const float* __restrict__ b1a,
                const float* __restrict__ W1b, const float* __restrict__ b1b,
                const float* __restrict__ W2a, const float* __restrict__ b2a,
                const float* __restrict__ W2b, const float* __restrict__ b2b,
                float* __restrict__ out, float* __restrict__ lam_out)
{
    const int row  = blockIdx.x;
    const int tid  = threadIdx.x;
    const int lane = tid & 31;
    const int warp = tid >> 5;
    const unsigned FULL = 0xffffffffu;

    __shared__ float s_d[K_], s_lk[K_], s_ls[K_], s_cnt[K_], s_probs[K_];
    __shared__ int   s_idx[K_];
    __shared__ float s_warp[NW][8];
    __shared__ float s_top8[8];
    __shared__ float s_lam;

    // ---- Phase 1 (warp 0): per-row small inputs + distinct-label prefix counts
    if (warp == 0) {
        const int base = row * K_;
        int v = tgt[base + lane];
        s_idx[lane] = v;
        s_d[lane]  = dists[base + lane];
        s_lk[lane] = logf(keyf[base + lane]);
        s_ls[lane] = logf(selp[base + lane]);
        bool dup = false;
        #pragma unroll
        for (int j = 0; j < 31; ++j) {
            int vj = __shfl_sync(FULL, v, j);
            if (j < lane && vj == v) dup = true;
        }
        unsigned m = __ballot_sync(FULL, (v != 0) && !dup);
        s_cnt[lane] = (float)__popc(m & ((2u << lane) - 1u));
    }

    // ---- Phase 2: READ-ONLY streaming scan, packed bf16x2 top-8
    // (output zeroing done by the memset node at pure-write BW)
    const float4* src = reinterpret_cast<const float4*>(nprob + (size_t)row * V_);

    unsigned tp[8];
    #pragma unroll
    for (int j = 0; j < 8; ++j) tp[j] = 0u;   // packed +0,+0 — below all probs

    #pragma unroll 1
    for (int k = 0; k < 8; ++k) {
        int i = tid + k * 4 * NT;
        float4 a = __ldcs(src + i);
        float4 b = __ldcs(src + i + NT);
        float4 c = __ldcs(src + i + 2 * NT);
        float4 d;
        if (k < 7 || tid < 64) d = __ldcs(src + i + 3 * NT);   // last strip: tid<64 only
        else                   d = make_float4(-1.f, -1.f, -1.f, -1.f);
        unsigned p[8];
        p[0] = packhi(a.x, a.y); p[1] = packhi(a.z, a.w);
        p[2] = packhi(b.x, b.y); p[3] = packhi(b.z, b.w);
        p[4] = packhi(c.x, c.y); p[5] = packhi(c.z, c.w);
        p[6] = packhi(d.x, d.y); p[7] = packhi(d.z, d.w);
        fold8p(p, tp);
    }

    // Unpack the two half-streams (both descending), merge to per-thread f32 top-8.
    float t[8];
    {
        float lo[8], hi[8];
        #pragma unroll
        for (int j = 0; j < 8; ++j) {
            lo[j] = __uint_as_float(tp[j] << 16);
            hi[j] = __uint_as_float(tp[j] & 0xFFFF0000u);
        }
        top8_of_two8f(lo, hi, t);
    }

    // ---- Phase 3: register/shuffle top-8 reduction (f32)
    #pragma unroll
    for (int off = 16; off >= 1; off >>= 1) {
        float b[8];
        #pragma unroll
        for (int j = 0; j < 8; ++j) b[j] = __shfl_down_sync(FULL, t[j], off);
        merge8f(t, b);
    }
    if (lane == 0) {
        #pragma unroll
        for (int j = 0; j < 8; ++j) s_warp[warp][j] = t[j];
    }
    __syncthreads();

    if (warp == 0) {
        float w[8];
        #pragma unroll
        for (int j = 0; j < 8; ++j) w[j] = (lane < NW) ? s_warp[lane & (NW - 1)][j] : -1.0f;
        #pragma unroll
        for (int off = 4; off >= 1; off >>= 1) {
            float b[8];
            #pragma unroll
            for (int j = 0; j < 8; ++j) b[j] = __shfl_down_sync(FULL, w[j], off);
            merge8f(w, b);
        }
        if (lane == 0) {
            #pragma unroll
            for (int j = 0; j < 8; ++j) s_top8[j] = w[j];
        }
        __syncwarp();

        // ---- Phase 4 (warp 0): MLPs, softmax, lambda
        float lk = s_lk[lane], ls = s_ls[lane], d = s_d[lane];

        float nl = b1b[0];
        #pragma unroll
        for (int j = 0; j < 4; ++j) {
            float h = tanhf(fmaf(W1a[2 * j], lk, fmaf(W1a[2 * j + 1], ls, b1a[j])));
            nl = fmaf(W1b[j], h, nl);
        }

        float acc = b2a[lane];
        #pragma unroll
        for (int dd = 0; dd < 32; ++dd) acc = fmaf(W2a[lane * 64 + dd],      s_d[dd],   acc);
        #pragma unroll
        for (int dd = 0; dd < 32; ++dd) acc = fmaf(W2a[lane * 64 + 32 + dd], s_cnt[dd], acc);
        float h2 = tanhf(acc);
        float l0 = W2b[lane]      * h2;
        float l1 = W2b[32 + lane] * h2;

        float sp = fmaf(Wf[8 + lane], lk, Wf[40 + lane] * ls);
        if (lane < 8) sp = fmaf(Wf[lane], logf(s_top8[lane]), sp);

        #pragma unroll
        for (int o = 16; o >= 1; o >>= 1) {
            l0 += __shfl_xor_sync(FULL, l0, o);
            l1 += __shfl_xor_sync(FULL, l1, o);
            sp += __shfl_xor_sync(FULL, sp, o);
        }
        l0 += b2b[0]; l1 += b2b[1];
        float sim   = sp + bf[0];
        float tempe = 1.f / (1.f + expf(-l1));

        float z  = fmaf(-d, tempe, nl);
        float mx = z;
        #pragma unroll
        for (int o = 16; o >= 1; o >>= 1) mx = fmaxf(mx, __shfl_xor_sync(FULL, mx, o));
        float e  = expf(z - mx);
        float se = e;
        #pragma unroll
        for (int o = 16; o >= 1; o >>= 1) se += __shfl_xor_sync(FULL, se, o);
        s_probs[lane] = e / se;

        if (lane == 0) s_lam = 1.f / (1.f + expf(-(l0 - sim)));

        __syncwarp();

        // ---- Phase 5: ordered scatter (last-wins for duplicates) + lambda
        // Output row was zeroed by the memset node (stream-ordered before us).
        if (lane == 0) {
            float* orow = out + (size_t)row * V_;
            #pragma unroll
            for (int k = 0; k < K_; ++k) orow[s_idx[k]] = s_probs[k];
            lam_out[row] = s_lam;
        }
    }
}

extern "C" void kernel_launch(void* const* d_in, const int* in_sizes, int n_in,
                              void* d_out, int out_size) {
    const int*   tgt   = (const int*)  d_in[0];
    const float* dists = (const float*)d_in[1];
    const float* keyf  = (const float*)d_in[2];
    const float* nprob = (const float*)d_in[3];
    const float* selp  = (const float*)d_in[4];
    const float* Wf    = (const float*)d_in[5];
    const float* bf    = (const float*)d_in[6];
    const float* W1a   = (const float*)d_in[7];
    const float* b1a   = (const float*)d_in[8];
    const float* W1b   = (const float*)d_in[9];
    const float* b1b   = (const float*)d_in[10];
    const float* W2a   = (const float*)d_in[11];
    const float* b2a   = (const float*)d_in[12];
    const float* W2b   = (const float*)d_in[13];
    const float* b2b   = (const float*)d_in[14];

    float* out = (float*)d_out;
    float* lam = out + ((size_t)out_size - ROWS);

    // Zero knn_prob at pure-write bandwidth; stream order guarantees
    // completion before the scan kernel's scatter.
    cudaMemsetAsync(out, 0, (size_t)ROWS * V_ * sizeof(float));

    combiner_kernel<<<ROWS, NT>>>(tgt, dists, keyf, nprob, selp,
                                  Wf, bf, W1a, b1a, W1b, b1b,
                                  W2a, b2a, W2b, b2b, out, lam);
}